// round 1
// baseline (speedup 1.0000x reference)
#include <cuda_runtime.h>
#include <math.h>

// Problem constants
#define NTOK  65536
#define EFULL 512
#define HIDC  256
#define NGR   4096
#define GSZ   16
#define KA    514          // E + 2

// ---------------- scratch (__device__ globals; no allocation allowed) ----------
__device__ float g_h1[NTOK * HIDC];          // 64 MB
__device__ float g_h2[NTOK * HIDC];          // 64 MB
__device__ float g_key1[NTOK * EFULL];       // 128 MB
__device__ float g_qkv[NTOK * 3 * EFULL];    // 384 MB
__device__ float g_omean[NGR * EFULL];
__device__ float g_km[NGR * EFULL];
__device__ float g_hga[NGR * HIDC];
__device__ float g_hgb[NGR * HIDC];
__device__ float g_alt[NTOK * EFULL];        // 128 MB

__device__ __forceinline__ float elu1(float x) {
    return x > 0.f ? x : (expf(x) - 1.f);
}

// ---------------- generic NT GEMM: C[m,n] = epi(sum_k A[m,k]*B[n,k] + bias[n])
// A: MxK row-major, B: NxK row-major. Requires M%64==0, N%64==0. K arbitrary.
// EPI: 0 = none, 1 = elu, 2 = elu(elu(x))
template <int EPI>
__global__ __launch_bounds__(256) void gemm_nt(
    const float* __restrict__ A, const float* __restrict__ B,
    const float* __restrict__ bias, float* __restrict__ C,
    int M, int Nn, int K)
{
    __shared__ float As[16][65];
    __shared__ float Bs[16][65];
    const int m0 = blockIdx.y * 64;
    const int n0 = blockIdx.x * 64;
    const int tid = threadIdx.x;
    const int ty = tid >> 4;     // 0..15 (row group)
    const int tx = tid & 15;     // 0..15 (col group)

    float acc[4][4] = {};

    for (int k0 = 0; k0 < K; k0 += 16) {
#pragma unroll
        for (int i = 0; i < 4; i++) {
            int idx = tid + i * 256;        // 0..1023
            int r  = idx >> 4;              // 0..63
            int kk = idx & 15;              // 0..15
            int gk = k0 + kk;
            float av = 0.f, bv = 0.f;
            if (gk < K) {
                av = A[(size_t)(m0 + r) * K + gk];
                bv = B[(size_t)(n0 + r) * K + gk];
            }
            As[kk][r] = av;
            Bs[kk][r] = bv;
        }
        __syncthreads();
#pragma unroll
        for (int kk = 0; kk < 16; kk++) {
            float a[4], b[4];
#pragma unroll
            for (int i = 0; i < 4; i++) a[i] = As[kk][ty * 4 + i];
#pragma unroll
            for (int j = 0; j < 4; j++) b[j] = Bs[kk][tx * 4 + j];
#pragma unroll
            for (int i = 0; i < 4; i++)
#pragma unroll
                for (int j = 0; j < 4; j++)
                    acc[i][j] += a[i] * b[j];
        }
        __syncthreads();
    }

#pragma unroll
    for (int i = 0; i < 4; i++) {
        int m = m0 + ty * 4 + i;
#pragma unroll
        for (int j = 0; j < 4; j++) {
            int n = n0 + tx * 4 + j;
            float v = acc[i][j] + bias[n];
            if (EPI == 1) v = elu1(v);
            else if (EPI == 2) v = elu1(elu1(v));
            C[(size_t)m * Nn + n] = v;
        }
    }
}

// ---------------- per-group attention (mean over seq folded into column weights)
// qkv: [NTOK, 1536] with q|k|v each 512 wide. omean: [NGR, 512].
// o_mean[g, h*256+d] = sum_tk ( (1/16) sum_tq softmax_row(scores)[tq,tk] ) * v[tk, h*256+d]
__global__ __launch_bounds__(256) void attn_kernel(
    const float* __restrict__ qkv, float* __restrict__ omean)
{
    const int g = blockIdx.x;
    const int tid = threadIdx.x;
    __shared__ float qs[16][257];
    __shared__ float ks[16][257];
    __shared__ float sc[16][17];
    __shared__ float cw[16];
    const float* base = qkv + (size_t)g * GSZ * 1536;

    for (int h = 0; h < 2; h++) {
        // load q,k for this head (16 x 256 each)
        for (int i = tid; i < 16 * 256; i += 256) {
            int t = i >> 8, d = i & 255;
            qs[t][d] = base[t * 1536 + h * 256 + d];
            ks[t][d] = base[t * 1536 + 512 + h * 256 + d];
        }
        __syncthreads();
        // scores: one (tq, tk) per thread
        {
            int tq = tid >> 4, tk = tid & 15;
            float acc = 0.f;
#pragma unroll 8
            for (int d = 0; d < 256; d++) acc += qs[tq][d] * ks[tk][d];
            sc[tq][tk] = acc * 0.0625f;   // 1/sqrt(256)
        }
        __syncthreads();
        // softmax per row
        if (tid < 16) {
            int tq = tid;
            float mx = -1e30f;
            for (int tk = 0; tk < 16; tk++) mx = fmaxf(mx, sc[tq][tk]);
            float sum = 0.f;
            for (int tk = 0; tk < 16; tk++) {
                float e = expf(sc[tq][tk] - mx);
                sc[tq][tk] = e;
                sum += e;
            }
            float inv = 1.f / sum;
            for (int tk = 0; tk < 16; tk++) sc[tq][tk] *= inv;
        }
        __syncthreads();
        // column means
        if (tid < 16) {
            int tk = tid;
            float s = 0.f;
            for (int tq = 0; tq < 16; tq++) s += sc[tq][tk];
            cw[tk] = s * 0.0625f;          // mean over 16 queries
        }
        __syncthreads();
        // o_mean for this head: one d per thread
        {
            int d = tid;
            float acc = 0.f;
#pragma unroll
            for (int tk = 0; tk < 16; tk++)
                acc += cw[tk] * base[tk * 1536 + 1024 + h * 256 + d];
            omean[(size_t)g * EFULL + h * 256 + d] = acc;
        }
        __syncthreads();
    }
}

// ---------------- g head final: q_jt[g] = dot(hg[g], w4) + b4   (256 -> 1)
__global__ __launch_bounds__(256) void ghead4_kernel(
    const float* __restrict__ hg, const float* __restrict__ w,
    const float* __restrict__ b, float* __restrict__ out)
{
    int row = blockIdx.x * 8 + (threadIdx.x >> 5);
    int lane = threadIdx.x & 31;
    float acc = 0.f;
    for (int k = lane; k < 256; k += 32)
        acc += hg[(size_t)row * 256 + k] * w[k];
#pragma unroll
    for (int o = 16; o > 0; o >>= 1)
        acc += __shfl_xor_sync(0xffffffffu, acc, o);
    if (lane == 0) out[row] = acc + b[0];
}

// ---------------- alt_val = pe + km[group] - key1/16  (elementwise, N x 512)
__global__ __launch_bounds__(256) void altval_kernel(
    const float* __restrict__ pe, const float* __restrict__ key1,
    const float* __restrict__ km, float* __restrict__ alt)
{
    size_t i = (size_t)blockIdx.x * blockDim.x + threadIdx.x;
    int d = (int)(i & 511);
    size_t m = i >> 9;
    size_t g = m >> 4;
    alt[i] = pe[i] + km[g * EFULL + d] - key1[i] * 0.0625f;
}

// ---------------- alt_q = hp @ w3^T + b3 (256 -> 2)
__global__ __launch_bounds__(256) void altq_kernel(
    const float* __restrict__ hp, const float* __restrict__ w,
    const float* __restrict__ b, float* __restrict__ out)
{
    int row = blockIdx.x * 8 + (threadIdx.x >> 5);
    int lane = threadIdx.x & 31;
    float a0 = 0.f, a1 = 0.f;
    for (int k = lane; k < 256; k += 32) {
        float h = hp[(size_t)row * 256 + k];
        a0 += h * w[k];
        a1 += h * w[256 + k];
    }
#pragma unroll
    for (int o = 16; o > 0; o >>= 1) {
        a0 += __shfl_xor_sync(0xffffffffu, a0, o);
        a1 += __shfl_xor_sync(0xffffffffu, a1, o);
    }
    if (lane == 0) {
        out[(size_t)row * 2 + 0] = a0 + b[0];
        out[(size_t)row * 2 + 1] = a1 + b[1];
    }
}

// ================================================================ host launch
extern "C" void kernel_launch(void* const* d_in, const int* in_sizes, int n_in,
                              void* d_out, int out_size)
{
    const float* pe       = (const float*)d_in[0];   // (N, 512)
    const float* peA      = (const float*)d_in[1];   // (N, 514)
    const float* attn_in_w  = (const float*)d_in[2]; // (1536, 512)
    const float* attn_in_b  = (const float*)d_in[3];
    const float* attn_out_w = (const float*)d_in[4]; // (512, 512)
    const float* attn_out_b = (const float*)d_in[5];
    const float* p1w1 = (const float*)d_in[6];  const float* p1b1 = (const float*)d_in[7];
    const float* p1w2 = (const float*)d_in[8];  const float* p1b2 = (const float*)d_in[9];
    const float* p1w3 = (const float*)d_in[10]; const float* p1b3 = (const float*)d_in[11];
    const float* p1w4 = (const float*)d_in[12]; const float* p1b4 = (const float*)d_in[13];
    const float* gw1 = (const float*)d_in[14];  const float* gb1 = (const float*)d_in[15];
    const float* gw2 = (const float*)d_in[16];  const float* gb2 = (const float*)d_in[17];
    const float* gw3 = (const float*)d_in[18];  const float* gb3 = (const float*)d_in[19];
    const float* gw4 = (const float*)d_in[20];  const float* gb4 = (const float*)d_in[21];
    const float* p2w1 = (const float*)d_in[22]; const float* p2b1 = (const float*)d_in[23];
    const float* p2w2 = (const float*)d_in[24]; const float* p2b2 = (const float*)d_in[25];
    const float* p2w3 = (const float*)d_in[26]; const float* p2b3 = (const float*)d_in[27];
    float* out = (float*)d_out;

    float *h1, *h2, *key1, *qkv, *omean, *km, *hga, *hgb, *alt;
    cudaGetSymbolAddress((void**)&h1,    g_h1);
    cudaGetSymbolAddress((void**)&h2,    g_h2);
    cudaGetSymbolAddress((void**)&key1,  g_key1);
    cudaGetSymbolAddress((void**)&qkv,   g_qkv);
    cudaGetSymbolAddress((void**)&omean, g_omean);
    cudaGetSymbolAddress((void**)&km,    g_km);
    cudaGetSymbolAddress((void**)&hga,   g_hga);
    cudaGetSymbolAddress((void**)&hgb,   g_hgb);
    cudaGetSymbolAddress((void**)&alt,   g_alt);

    const int TB = 256;

    // phi1 chain
    gemm_nt<1><<<dim3(HIDC / 64, NTOK / 64), TB>>>(peA, p1w1, p1b1, h1, NTOK, HIDC, KA);
    gemm_nt<2><<<dim3(HIDC / 64, NTOK / 64), TB>>>(h1, p1w2, p1b2, h2, NTOK, HIDC, HIDC);
    gemm_nt<1><<<dim3(HIDC / 64, NTOK / 64), TB>>>(h2, p1w3, p1b3, h1, NTOK, HIDC, HIDC);
    gemm_nt<0><<<dim3(EFULL / 64, NTOK / 64), TB>>>(h1, p1w4, p1b4, key1, NTOK, EFULL, HIDC);

    // qkv projection + attention (mean-pooled)
    gemm_nt<0><<<dim3(1536 / 64, NTOK / 64), TB>>>(key1, attn_in_w, attn_in_b, qkv, NTOK, 1536, EFULL);
    attn_kernel<<<NGR, TB>>>(qkv, omean);
    gemm_nt<0><<<dim3(EFULL / 64, NGR / 64), TB>>>(omean, attn_out_w, attn_out_b, km, NGR, EFULL, EFULL);

    // g head -> q_jt at out[0 .. 4096)
    gemm_nt<1><<<dim3(HIDC / 64, NGR / 64), TB>>>(km, gw1, gb1, hga, NGR, HIDC, EFULL);
    gemm_nt<1><<<dim3(HIDC / 64, NGR / 64), TB>>>(hga, gw2, gb2, hgb, NGR, HIDC, HIDC);
    gemm_nt<1><<<dim3(HIDC / 64, NGR / 64), TB>>>(hgb, gw3, gb3, hga, NGR, HIDC, HIDC);
    ghead4_kernel<<<NGR / 8, TB>>>(hga, gw4, gb4, out);

    // alt path -> alt_q at out[4096 ..)
    altval_kernel<<<(NTOK * (size_t)EFULL) / TB, TB>>>(pe, key1, km, alt);
    gemm_nt<1><<<dim3(HIDC / 64, NTOK / 64), TB>>>(alt, p2w1, p2b1, h1, NTOK, HIDC, EFULL);
    gemm_nt<1><<<dim3(HIDC / 64, NTOK / 64), TB>>>(h1, p2w2, p2b2, h2, NTOK, HIDC, HIDC);
    altq_kernel<<<NTOK / 8, TB>>>(h2, p2w3, p2b3, out + NGR);
}

// round 3
// speedup vs baseline: 4.1956x; 4.1956x over previous
#include <cuda_runtime.h>
#include <cuda_bf16.h>
#include <cstdint>
#include <math.h>

// Problem constants
#define NTOK  65536
#define EFULL 512
#define HIDC  256
#define NGR   4096
#define GSZ   16

// ---------------- scratch (__device__ globals; no allocation allowed) ----------
__device__ float g_h1[NTOK * HIDC];
__device__ float g_h2[NTOK * HIDC];
__device__ float g_key1[NTOK * EFULL];
__device__ float g_qk[NTOK * 1024];          // q|k per token
__device__ float g_xw[2 * NGR * EFULL];      // per-head weighted x
__device__ float g_omean[NGR * EFULL];
__device__ float g_km[NGR * EFULL];
__device__ float g_hga[NGR * HIDC];
__device__ float g_hgb[NGR * HIDC];
__device__ float g_alt[NTOK * EFULL];

__device__ __forceinline__ float elu1(float x) {
    return x > 0.f ? x : (expf(x) - 1.f);
}

__device__ __forceinline__ uint32_t smem_u32(const void* p) {
    uint32_t a;
    asm("{ .reg .u64 t; cvta.to.shared.u64 t, %1; cvt.u32.u64 %0, t; }" : "=r"(a) : "l"(p));
    return a;
}

__device__ __forceinline__ void ldsm4(uint32_t& r0, uint32_t& r1, uint32_t& r2, uint32_t& r3,
                                      uint32_t addr) {
    asm volatile("ldmatrix.sync.aligned.m8n8.x4.shared.b16 {%0,%1,%2,%3}, [%4];"
                 : "=r"(r0), "=r"(r1), "=r"(r2), "=r"(r3) : "r"(addr));
}

__device__ __forceinline__ void mma16816(float* c, const uint32_t* a, const uint32_t* b) {
    asm volatile("mma.sync.aligned.m16n8k16.row.col.f32.bf16.bf16.f32 "
                 "{%0,%1,%2,%3}, {%4,%5,%6,%7}, {%8,%9}, {%0,%1,%2,%3};"
                 : "+f"(c[0]), "+f"(c[1]), "+f"(c[2]), "+f"(c[3])
                 : "r"(a[0]), "r"(a[1]), "r"(a[2]), "r"(a[3]), "r"(b[0]), "r"(b[1]));
}

__device__ __forceinline__ void cvt_split2(float a, float b, uint32_t& hi, uint32_t& lo) {
    __nv_bfloat162 h = __floats2bfloat162_rn(a, b);
    float2 hf = __bfloat1622float2(h);
    __nv_bfloat162 l = __floats2bfloat162_rn(a - hf.x, b - hf.y);
    hi = *reinterpret_cast<uint32_t*>(&h);
    lo = *reinterpret_cast<uint32_t*>(&l);
}

// ======== HMMA NT GEMM: C[m, n] = epi(sum_k A[m,k]*B[n,k] + bias[n]) =========
// A: MxK fp32 row-major, B: NxK fp32 row-major. M%128==0, N%128==0, K arbitrary.
// C has row stride ldC. 3-pass bf16 split for fp32-like accuracy.
// EPI: 0 none, 1 elu, 2 elu(elu)
#define SA 40   // smem row stride in bf16 elems (80 bytes -> conflict-free ldmatrix)

template <int EPI>
__global__ __launch_bounds__(256, 1) void gemm_mma(
    const float* __restrict__ A, const float* __restrict__ B,
    const float* __restrict__ bias, float* __restrict__ C,
    int M, int Nn, int K, int ldC)
{
    __shared__ __align__(16) __nv_bfloat16 sAh[128 * SA];
    __shared__ __align__(16) __nv_bfloat16 sAl[128 * SA];
    __shared__ __align__(16) __nv_bfloat16 sBh[128 * SA];
    __shared__ __align__(16) __nv_bfloat16 sBl[128 * SA];

    const int tid = threadIdx.x;
    const int lane = tid & 31;
    const int wid = tid >> 5;
    const int wm = wid & 3;       // 4 warps in M
    const int wn = wid >> 2;      // 2 warps in N
    const int m0 = blockIdx.y * 128;
    const int n0 = blockIdx.x * 128;

    const uint32_t bAh = smem_u32(sAh), bAl = smem_u32(sAl);
    const uint32_t bBh = smem_u32(sBh), bBl = smem_u32(sBl);

    float acc[2][8][4] = {};
    float4 av[4], bv[4];

    const int nch = (K + 31) >> 5;
    const bool vec = (K & 31) == 0;

    const int lr = tid >> 3;       // 0..31 (but we index per-j)
    const int lc = tid & 7;
    (void)lr;

    // ---- prefetch chunk 0 ----
    {
        const int k0 = 0;
#pragma unroll
        for (int j = 0; j < 4; j++) {
            int idx = tid + j * 256;
            int r = idx >> 3, c4 = idx & 7;
            if (vec) {
                av[j] = *reinterpret_cast<const float4*>(A + (size_t)(m0 + r) * K + k0 + c4 * 4);
                bv[j] = *reinterpret_cast<const float4*>(B + (size_t)(n0 + r) * K + k0 + c4 * 4);
            } else {
                float ta[4], tb[4];
#pragma unroll
                for (int e = 0; e < 4; e++) {
                    int kk = k0 + c4 * 4 + e;
                    ta[e] = (kk < K) ? A[(size_t)(m0 + r) * K + kk] : 0.f;
                    tb[e] = (kk < K) ? B[(size_t)(n0 + r) * K + kk] : 0.f;
                }
                av[j] = make_float4(ta[0], ta[1], ta[2], ta[3]);
                bv[j] = make_float4(tb[0], tb[1], tb[2], tb[3]);
            }
        }
    }

    for (int ci = 0; ci < nch; ci++) {
        __syncthreads();   // previous chunk's compute done -> smem reusable
        // ---- split + store to smem ----
#pragma unroll
        for (int j = 0; j < 4; j++) {
            int idx = tid + j * 256;
            int r = idx >> 3, c4 = idx & 7;
            uint32_t o = (uint32_t)(r * SA + c4 * 4) * 2;   // bytes
            uint32_t h01, l01, h23, l23;
            cvt_split2(av[j].x, av[j].y, h01, l01);
            cvt_split2(av[j].z, av[j].w, h23, l23);
            *reinterpret_cast<uint2*>((char*)sAh + o) = make_uint2(h01, h23);
            *reinterpret_cast<uint2*>((char*)sAl + o) = make_uint2(l01, l23);
            cvt_split2(bv[j].x, bv[j].y, h01, l01);
            cvt_split2(bv[j].z, bv[j].w, h23, l23);
            *reinterpret_cast<uint2*>((char*)sBh + o) = make_uint2(h01, h23);
            *reinterpret_cast<uint2*>((char*)sBl + o) = make_uint2(l01, l23);
        }
        __syncthreads();

        // ---- prefetch next chunk (overlaps with compute below) ----
        if (ci + 1 < nch) {
            const int k0 = (ci + 1) << 5;
#pragma unroll
            for (int j = 0; j < 4; j++) {
                int idx = tid + j * 256;
                int r = idx >> 3, c4 = idx & 7;
                if (vec) {
                    av[j] = *reinterpret_cast<const float4*>(A + (size_t)(m0 + r) * K + k0 + c4 * 4);
                    bv[j] = *reinterpret_cast<const float4*>(B + (size_t)(n0 + r) * K + k0 + c4 * 4);
                } else {
                    float ta[4], tb[4];
#pragma unroll
                    for (int e = 0; e < 4; e++) {
                        int kk = k0 + c4 * 4 + e;
                        ta[e] = (kk < K) ? A[(size_t)(m0 + r) * K + kk] : 0.f;
                        tb[e] = (kk < K) ? B[(size_t)(n0 + r) * K + kk] : 0.f;
                    }
                    av[j] = make_float4(ta[0], ta[1], ta[2], ta[3]);
                    bv[j] = make_float4(tb[0], tb[1], tb[2], tb[3]);
                }
            }
        }

        // ---- compute: 2 k-steps of 16, 3 passes ----
#pragma unroll
        for (int kk = 0; kk < 2; kk++) {
            uint32_t ah[2][4], al_[2][4];
            {
                int ar = lane & 15;
                int akc = ((lane >> 4) << 3) + (kk << 4);   // elems
#pragma unroll
                for (int i = 0; i < 2; i++) {
                    uint32_t off = (uint32_t)((wm * 32 + i * 16 + ar) * SA + akc) * 2;
                    ldsm4(ah[i][0], ah[i][1], ah[i][2], ah[i][3], bAh + off);
                    ldsm4(al_[i][0], al_[i][1], al_[i][2], al_[i][3], bAl + off);
                }
            }
            uint32_t bh[8][2], bl_[8][2];
            {
                int br = (lane & 7) + ((lane >> 4) & 1) * 8;
                int bkc = (((lane >> 3) & 1) << 3) + (kk << 4);
#pragma unroll
                for (int jf = 0; jf < 4; jf++) {
                    uint32_t off = (uint32_t)((wn * 64 + jf * 16 + br) * SA + bkc) * 2;
                    uint32_t r0, r1, r2, r3;
                    ldsm4(r0, r1, r2, r3, bBh + off);
                    bh[2 * jf][0] = r0; bh[2 * jf][1] = r1;
                    bh[2 * jf + 1][0] = r2; bh[2 * jf + 1][1] = r3;
                    ldsm4(r0, r1, r2, r3, bBl + off);
                    bl_[2 * jf][0] = r0; bl_[2 * jf][1] = r1;
                    bl_[2 * jf + 1][0] = r2; bl_[2 * jf + 1][1] = r3;
                }
            }
#pragma unroll
            for (int i = 0; i < 2; i++)
#pragma unroll
                for (int j = 0; j < 8; j++)
                    mma16816(acc[i][j], ah[i], bh[j]);
#pragma unroll
            for (int i = 0; i < 2; i++)
#pragma unroll
                for (int j = 0; j < 8; j++)
                    mma16816(acc[i][j], ah[i], bl_[j]);
#pragma unroll
            for (int i = 0; i < 2; i++)
#pragma unroll
                for (int j = 0; j < 8; j++)
                    mma16816(acc[i][j], al_[i], bh[j]);
        }
    }

    // ---- epilogue: bias + ELU, direct stores ----
#pragma unroll
    for (int i = 0; i < 2; i++) {
        int row = m0 + wm * 32 + i * 16 + (lane >> 2);
#pragma unroll
        for (int j = 0; j < 8; j++) {
            int col = n0 + wn * 64 + j * 8 + (lane & 3) * 2;
            float b0 = bias[col], b1 = bias[col + 1];
            float v0 = acc[i][j][0] + b0, v1 = acc[i][j][1] + b1;
            float v2 = acc[i][j][2] + b0, v3 = acc[i][j][3] + b1;
            if (EPI >= 1) { v0 = elu1(v0); v1 = elu1(v1); v2 = elu1(v2); v3 = elu1(v3); }
            if (EPI == 2) { v0 = elu1(v0); v1 = elu1(v1); v2 = elu1(v2); v3 = elu1(v3); }
            *reinterpret_cast<float2*>(C + (size_t)row * ldC + col) = make_float2(v0, v1);
            *reinterpret_cast<float2*>(C + (size_t)(row + 8) * ldC + col) = make_float2(v2, v3);
        }
    }
}

// ---------------- attention: scores from q,k; softmax; column-mean weights;
// per-head weighted sum of x -> xw[h][g][512]
__global__ __launch_bounds__(256) void attn2_kernel(
    const float* __restrict__ qk, const float* __restrict__ x,
    float* __restrict__ xw)
{
    const int g = blockIdx.x;
    const int tid = threadIdx.x;
    __shared__ float qs[16][257];
    __shared__ float ks[16][257];
    __shared__ float sc[16][17];
    __shared__ float cw[16];
    const float* base = qk + (size_t)g * GSZ * 1024;
    const float* xbase = x + (size_t)g * GSZ * 512;

    for (int h = 0; h < 2; h++) {
        for (int i = tid; i < 16 * 256; i += 256) {
            int t = i >> 8, d = i & 255;
            qs[t][d] = base[t * 1024 + h * 256 + d];
            ks[t][d] = base[t * 1024 + 512 + h * 256 + d];
        }
        __syncthreads();
        {
            int tq = tid >> 4, tk = tid & 15;
            float a = 0.f;
#pragma unroll 8
            for (int d = 0; d < 256; d++) a += qs[tq][d] * ks[tk][d];
            sc[tq][tk] = a * 0.0625f;
        }
        __syncthreads();
        if (tid < 16) {
            int tq = tid;
            float mx = -1e30f;
            for (int tk = 0; tk < 16; tk++) mx = fmaxf(mx, sc[tq][tk]);
            float s = 0.f;
            for (int tk = 0; tk < 16; tk++) {
                float e = expf(sc[tq][tk] - mx);
                sc[tq][tk] = e;
                s += e;
            }
            float inv = 1.f / s;
            for (int tk = 0; tk < 16; tk++) sc[tq][tk] *= inv;
        }
        __syncthreads();
        if (tid < 16) {
            int tk = tid;
            float s = 0.f;
            for (int tq = 0; tq < 16; tq++) s += sc[tq][tk];
            cw[tk] = s * 0.0625f;
        }
        __syncthreads();
        // xw[h][g][d] = sum_tk cw[tk] * x[g*16+tk][d]
        for (int it = 0; it < 2; it++) {
            int d = tid + it * 256;
            float a = 0.f;
#pragma unroll
            for (int tk = 0; tk < 16; tk++)
                a += cw[tk] * xbase[tk * 512 + d];
            xw[(size_t)h * NGR * EFULL + (size_t)g * EFULL + d] = a;
        }
        __syncthreads();
    }
}

// ---------------- g head final: q_jt[g] = dot(hg[g], w4) + b4
__global__ __launch_bounds__(256) void ghead4_kernel(
    const float* __restrict__ hg, const float* __restrict__ w,
    const float* __restrict__ b, float* __restrict__ out)
{
    int row = blockIdx.x * 8 + (threadIdx.x >> 5);
    int lane = threadIdx.x & 31;
    float acc = 0.f;
    for (int k = lane; k < 256; k += 32)
        acc += hg[(size_t)row * 256 + k] * w[k];
#pragma unroll
    for (int o = 16; o > 0; o >>= 1)
        acc += __shfl_xor_sync(0xffffffffu, acc, o);
    if (lane == 0) out[row] = acc + b[0];
}

// ---------------- alt_val = pe + km[group] - key1/16
__global__ __launch_bounds__(256) void altval_kernel(
    const float* __restrict__ pe, const float* __restrict__ key1,
    const float* __restrict__ km, float* __restrict__ alt)
{
    size_t i = (size_t)blockIdx.x * blockDim.x + threadIdx.x;
    int d = (int)(i & 511);
    size_t m = i >> 9;
    size_t g = m >> 4;
    alt[i] = pe[i] + km[g * EFULL + d] - key1[i] * 0.0625f;
}

// ---------------- alt_q = hp @ w3^T + b3 (256 -> 2)
__global__ __launch_bounds__(256) void altq_kernel(
    const float* __restrict__ hp, const float* __restrict__ w,
    const float* __restrict__ b, float* __restrict__ out)
{
    int row = blockIdx.x * 8 + (threadIdx.x >> 5);
    int lane = threadIdx.x & 31;
    float a0 = 0.f, a1 = 0.f;
    for (int k = lane; k < 256; k += 32) {
        float h = hp[(size_t)row * 256 + k];
        a0 += h * w[k];
        a1 += h * w[256 + k];
    }
#pragma unroll
    for (int o = 16; o > 0; o >>= 1) {
        a0 += __shfl_xor_sync(0xffffffffu, a0, o);
        a1 += __shfl_xor_sync(0xffffffffu, a1, o);
    }
    if (lane == 0) {
        out[(size_t)row * 2 + 0] = a0 + b[0];
        out[(size_t)row * 2 + 1] = a1 + b[1];
    }
}

// ================================================================ host launch
extern "C" void kernel_launch(void* const* d_in, const int* in_sizes, int n_in,
                              void* d_out, int out_size)
{
    const float* pe       = (const float*)d_in[0];
    const float* peA      = (const float*)d_in[1];
    const float* attn_in_w  = (const float*)d_in[2];
    const float* attn_in_b  = (const float*)d_in[3];
    const float* attn_out_w = (const float*)d_in[4];
    const float* attn_out_b = (const float*)d_in[5];
    const float* p1w1 = (const float*)d_in[6];  const float* p1b1 = (const float*)d_in[7];
    const float* p1w2 = (const float*)d_in[8];  const float* p1b2 = (const float*)d_in[9];
    const float* p1w3 = (const float*)d_in[10]; const float* p1b3 = (const float*)d_in[11];
    const float* p1w4 = (const float*)d_in[12]; const float* p1b4 = (const float*)d_in[13];
    const float* gw1 = (const float*)d_in[14];  const float* gb1 = (const float*)d_in[15];
    const float* gw2 = (const float*)d_in[16];  const float* gb2 = (const float*)d_in[17];
    const float* gw3 = (const float*)d_in[18];  const float* gb3 = (const float*)d_in[19];
    const float* gw4 = (const float*)d_in[20];  const float* gb4 = (const float*)d_in[21];
    const float* p2w1 = (const float*)d_in[22]; const float* p2b1 = (const float*)d_in[23];
    const float* p2w2 = (const float*)d_in[24]; const float* p2b2 = (const float*)d_in[25];
    const float* p2w3 = (const float*)d_in[26]; const float* p2b3 = (const float*)d_in[27];
    float* out = (float*)d_out;

    float *h1, *h2, *key1, *qk, *xw, *omean, *km, *hga, *hgb, *alt;
    cudaGetSymbolAddress((void**)&h1,    g_h1);
    cudaGetSymbolAddress((void**)&h2,    g_h2);
    cudaGetSymbolAddress((void**)&key1,  g_key1);
    cudaGetSymbolAddress((void**)&qk,    g_qk);
    cudaGetSymbolAddress((void**)&xw,    g_xw);
    cudaGetSymbolAddress((void**)&omean, g_omean);
    cudaGetSymbolAddress((void**)&km,    g_km);
    cudaGetSymbolAddress((void**)&hga,   g_hga);
    cudaGetSymbolAddress((void**)&hgb,   g_hgb);
    cudaGetSymbolAddress((void**)&alt,   g_alt);

    const int TB = 256;
    #define GRID(Mv, Nv) dim3((Nv) / 128, (Mv) / 128)

    // phi1 chain
    gemm_mma<1><<<GRID(NTOK, HIDC), TB>>>(peA, p1w1, p1b1, h1, NTOK, HIDC, 514, HIDC);
    gemm_mma<2><<<GRID(NTOK, HIDC), TB>>>(h1, p1w2, p1b2, h2, NTOK, HIDC, HIDC, HIDC);
    gemm_mma<1><<<GRID(NTOK, HIDC), TB>>>(h2, p1w3, p1b3, h1, NTOK, HIDC, HIDC, HIDC);
    gemm_mma<0><<<GRID(NTOK, EFULL), TB>>>(h1, p1w4, p1b4, key1, NTOK, EFULL, HIDC, EFULL);

    // q,k projection (v eliminated algebraically)
    gemm_mma<0><<<GRID(NTOK, 1024), TB>>>(key1, attn_in_w, attn_in_b, qk, NTOK, 1024, EFULL, 1024);
    attn2_kernel<<<NGR, TB>>>(qk, key1, xw);
    // o_mean per head: xw_h @ Wv_h^T + bv_h  (block-diagonal)
    gemm_mma<0><<<GRID(NGR, 256), TB>>>(xw, attn_in_w + (size_t)1024 * 512,
                                        attn_in_b + 1024, omean, NGR, 256, EFULL, EFULL);
    gemm_mma<0><<<GRID(NGR, 256), TB>>>(xw + (size_t)NGR * EFULL, attn_in_w + (size_t)1280 * 512,
                                        attn_in_b + 1280, omean + 256, NGR, 256, EFULL, EFULL);
    // km = omean @ Wo^T + bo
    gemm_mma<0><<<GRID(NGR, EFULL), TB>>>(omean, attn_out_w, attn_out_b, km, NGR, EFULL, EFULL, EFULL);

    // g head -> q_jt at out[0 .. 4096)
    gemm_mma<1><<<GRID(NGR, HIDC), TB>>>(km, gw1, gb1, hga, NGR, HIDC, EFULL, HIDC);
    gemm_mma<1><<<GRID(NGR, HIDC), TB>>>(hga, gw2, gb2, hgb, NGR, HIDC, HIDC, HIDC);
    gemm_mma<1><<<GRID(NGR, HIDC), TB>>>(hgb, gw3, gb3, hga, NGR, HIDC, HIDC, HIDC);
    ghead4_kernel<<<NGR / 8, TB>>>(hga, gw4, gb4, out);

    // alt path -> alt_q at out[4096 ..)
    altval_kernel<<<(NTOK * (size_t)EFULL) / TB, TB>>>(pe, key1, km, alt);
    gemm_mma<1><<<GRID(NTOK, HIDC), TB>>>(alt, p2w1, p2b1, h1, NTOK, HIDC, EFULL, HIDC);
    gemm_mma<1><<<GRID(NTOK, HIDC), TB>>>(h1, p2w2, p2b2, h2, NTOK, HIDC, HIDC, HIDC);
    altq_kernel<<<NTOK / 8, TB>>>(h2, p2w3, p2b3, out + NGR);
}

// round 4
// speedup vs baseline: 4.5320x; 1.0802x over previous
#include <cuda_runtime.h>
#include <cuda_bf16.h>
#include <cstdint>
#include <math.h>

// Problem constants
#define NTOK  65536
#define EFULL 512
#define HIDC  256
#define NGR   4096
#define GSZ   16
#define KPAD1 544          // 514 padded to %32

// ---------------- scratch (__device__ globals) ----------------
__device__ __nv_bfloat16 g_peAh[(size_t)NTOK * KPAD1];
__device__ __nv_bfloat16 g_peAl[(size_t)NTOK * KPAD1];
__device__ __nv_bfloat16 g_h1h[(size_t)NTOK * HIDC];
__device__ __nv_bfloat16 g_h1l[(size_t)NTOK * HIDC];
__device__ __nv_bfloat16 g_h2h[(size_t)NTOK * HIDC];
__device__ __nv_bfloat16 g_h2l[(size_t)NTOK * HIDC];
__device__ float         g_key1[(size_t)NTOK * EFULL];
__device__ __nv_bfloat16 g_key1h[(size_t)NTOK * EFULL];
__device__ __nv_bfloat16 g_key1l[(size_t)NTOK * EFULL];
__device__ float         g_qk[(size_t)NTOK * 1024];
__device__ __nv_bfloat16 g_xwh[(size_t)2 * NGR * EFULL];
__device__ __nv_bfloat16 g_xwl[(size_t)2 * NGR * EFULL];
__device__ __nv_bfloat16 g_omh[(size_t)NGR * EFULL];
__device__ __nv_bfloat16 g_oml[(size_t)NGR * EFULL];
__device__ float         g_km[(size_t)NGR * EFULL];
__device__ __nv_bfloat16 g_kmh[(size_t)NGR * EFULL];
__device__ __nv_bfloat16 g_kml[(size_t)NGR * EFULL];
__device__ __nv_bfloat16 g_hgah[(size_t)NGR * HIDC];
__device__ __nv_bfloat16 g_hgal[(size_t)NGR * HIDC];
__device__ __nv_bfloat16 g_hgbh[(size_t)NGR * HIDC];
__device__ __nv_bfloat16 g_hgbl[(size_t)NGR * HIDC];
__device__ float         g_hgaf[(size_t)NGR * HIDC];
__device__ __nv_bfloat16 g_alth[(size_t)NTOK * EFULL];
__device__ __nv_bfloat16 g_altl[(size_t)NTOK * EFULL];
__device__ float         g_h2f[(size_t)NTOK * HIDC];

// weight pool (split bf16). offsets in elements:
#define OW_P1W1 0                 // 256x544
#define OW_P1W2 139264            // 256x256
#define OW_P1W3 204800            // 256x256
#define OW_P1W4 270336            // 512x256
#define OW_WQK  401408            // 1024x512
#define OW_WV0  925696            // 256x512
#define OW_WV1  1056768           // 256x512
#define OW_WOUT 1187840           // 512x512
#define OW_GW1  1449984           // 256x512
#define OW_GW2  1581056           // 256x256
#define OW_GW3  1646592           // 256x256
#define OW_P2W1 1712128           // 256x512
#define OW_P2W2 1843200           // 256x256
#define OW_TOT  1908736
__device__ __nv_bfloat16 g_wph[OW_TOT];
__device__ __nv_bfloat16 g_wpl[OW_TOT];

__device__ __forceinline__ float elu1(float x) {
    return x > 0.f ? x : (expf(x) - 1.f);
}
__device__ __forceinline__ uint32_t smem_u32(const void* p) {
    uint32_t a;
    asm("{ .reg .u64 t; cvta.to.shared.u64 t, %1; cvt.u32.u64 %0, t; }" : "=r"(a) : "l"(p));
    return a;
}
__device__ __forceinline__ void ldsm4(uint32_t& r0, uint32_t& r1, uint32_t& r2, uint32_t& r3,
                                      uint32_t addr) {
    asm volatile("ldmatrix.sync.aligned.m8n8.x4.shared.b16 {%0,%1,%2,%3}, [%4];"
                 : "=r"(r0), "=r"(r1), "=r"(r2), "=r"(r3) : "r"(addr));
}
__device__ __forceinline__ void mma16816(float* c, const uint32_t* a, const uint32_t* b) {
    asm volatile("mma.sync.aligned.m16n8k16.row.col.f32.bf16.bf16.f32 "
                 "{%0,%1,%2,%3}, {%4,%5,%6,%7}, {%8,%9}, {%0,%1,%2,%3};"
                 : "+f"(c[0]), "+f"(c[1]), "+f"(c[2]), "+f"(c[3])
                 : "r"(a[0]), "r"(a[1]), "r"(a[2]), "r"(a[3]), "r"(b[0]), "r"(b[1]));
}
__device__ __forceinline__ void cvt_split2(float a, float b, uint32_t& hi, uint32_t& lo) {
    __nv_bfloat162 h = __floats2bfloat162_rn(a, b);
    float2 hf = __bfloat1622float2(h);
    __nv_bfloat162 l = __floats2bfloat162_rn(a - hf.x, b - hf.y);
    hi = *reinterpret_cast<uint32_t*>(&h);
    lo = *reinterpret_cast<uint32_t*>(&l);
}
__device__ __forceinline__ uint32_t swz(uint32_t x) { return x ^ ((x >> 3) & 0x70); }

#define CP16(dst, src) \
    asm volatile("cp.async.cg.shared.global [%0], [%1], 16;" :: "r"(dst), "l"(src))
#define CP_COMMIT() asm volatile("cp.async.commit_group;" ::: "memory")
#define CP_WAIT1()  asm volatile("cp.async.wait_group 1;" ::: "memory")
#define CP_WAIT0()  asm volatile("cp.async.wait_group 0;" ::: "memory")

// ======== HMMA NT GEMM with pre-split bf16 operands ==========================
// C[m,n] = epi(sum_k A[m,k]*B[n,k] + bias[n]); A,B given as bf16 hi/lo pairs.
// K % 32 == 0, M % 128 == 0, N % 128 == 0.
#define STAGE 32768
#define SMEM_TOT (3 * STAGE)

template <int EPI, bool WF32, bool WSPLIT>
__global__ __launch_bounds__(256, 2) void gemm_bf16(
    const __nv_bfloat16* __restrict__ Ah, const __nv_bfloat16* __restrict__ Al,
    const __nv_bfloat16* __restrict__ Bh, const __nv_bfloat16* __restrict__ Bl,
    const float* __restrict__ bias, float* __restrict__ C,
    __nv_bfloat16* __restrict__ Ch, __nv_bfloat16* __restrict__ Cl,
    int K, int ldC)
{
    extern __shared__ __align__(1024) char smem[];
    const uint32_t sb = smem_u32(smem);
    const int tid = threadIdx.x;
    const int lane = tid & 31;
    const int wid = tid >> 5;
    const int wm = wid & 3;
    const int wn = wid >> 2;
    const int m0 = blockIdx.y * 128;
    const int n0 = blockIdx.x * 128;

    const int nch = K >> 5;
    float acc[2][8][4] = {};

    // load indices (shared by A and B: 128 rows x 32 cols bf16 per array)
    const int lr = (tid >> 2);        // with j offset below
    const int lc = tid & 3;

    auto issue = [&](int ci, int stg) {
        const int k0 = ci << 5;
        const uint32_t so = sb + stg * STAGE;
#pragma unroll
        for (int j = 0; j < 2; j++) {
            int r = lr + j * 64;
            uint32_t d = swz((uint32_t)(r * 64 + lc * 16));
            size_t ao = (size_t)(m0 + r) * K + k0 + lc * 8;
            size_t bo = (size_t)(n0 + r) * K + k0 + lc * 8;
            CP16(so + d,         Ah + ao);
            CP16(so + 8192 + d,  Al + ao);
            CP16(so + 16384 + d, Bh + bo);
            CP16(so + 24576 + d, Bl + bo);
        }
        CP_COMMIT();
    };

    issue(0, 0);
    if (nch > 1) issue(1, 1);

    int stg = 0;
    for (int ci = 0; ci < nch; ci++) {
        if (ci + 1 < nch) { CP_WAIT1(); } else { CP_WAIT0(); }
        __syncthreads();
        if (ci + 2 < nch) {
            int ns = stg + 2; if (ns >= 3) ns -= 3;
            issue(ci + 2, ns);
        }
        const uint32_t so = sb + stg * STAGE;

#pragma unroll
        for (int kk = 0; kk < 2; kk++) {
            uint32_t ah[2][4], al_[2][4];
            {
                int ar = lane & 15;
                int akb = kk * 32 + ((lane >> 4) * 16);
#pragma unroll
                for (int i = 0; i < 2; i++) {
                    uint32_t off = swz((uint32_t)((wm * 32 + i * 16 + ar) * 64 + akb));
                    ldsm4(ah[i][0], ah[i][1], ah[i][2], ah[i][3], so + off);
                    ldsm4(al_[i][0], al_[i][1], al_[i][2], al_[i][3], so + 8192 + off);
                }
            }
            uint32_t bh[8][2], bl_[8][2];
            {
                int br = (lane & 7) + ((lane >> 4) & 1) * 8;
                int bkb = ((lane >> 3) & 1) * 16 + kk * 32;
#pragma unroll
                for (int jf = 0; jf < 4; jf++) {
                    uint32_t off = swz((uint32_t)((wn * 64 + jf * 16 + br) * 64 + bkb));
                    uint32_t r0, r1, r2, r3;
                    ldsm4(r0, r1, r2, r3, so + 16384 + off);
                    bh[2 * jf][0] = r0; bh[2 * jf][1] = r1;
                    bh[2 * jf + 1][0] = r2; bh[2 * jf + 1][1] = r3;
                    ldsm4(r0, r1, r2, r3, so + 24576 + off);
                    bl_[2 * jf][0] = r0; bl_[2 * jf][1] = r1;
                    bl_[2 * jf + 1][0] = r2; bl_[2 * jf + 1][1] = r3;
                }
            }
#pragma unroll
            for (int i = 0; i < 2; i++)
#pragma unroll
                for (int j = 0; j < 8; j++)
                    mma16816(acc[i][j], ah[i], bh[j]);
#pragma unroll
            for (int i = 0; i < 2; i++)
#pragma unroll
                for (int j = 0; j < 8; j++)
                    mma16816(acc[i][j], ah[i], bl_[j]);
#pragma unroll
            for (int i = 0; i < 2; i++)
#pragma unroll
                for (int j = 0; j < 8; j++)
                    mma16816(acc[i][j], al_[i], bh[j]);
        }
        stg++; if (stg == 3) stg = 0;
        __syncthreads();
    }

    // ---- epilogue ----
#pragma unroll
    for (int i = 0; i < 2; i++) {
        int row = m0 + wm * 32 + i * 16 + (lane >> 2);
#pragma unroll
        for (int j = 0; j < 8; j++) {
            int col = n0 + wn * 64 + j * 8 + (lane & 3) * 2;
            float b0 = bias[col], b1 = bias[col + 1];
            float v0 = acc[i][j][0] + b0, v1 = acc[i][j][1] + b1;
            float v2 = acc[i][j][2] + b0, v3 = acc[i][j][3] + b1;
            if (EPI >= 1) { v0 = elu1(v0); v1 = elu1(v1); v2 = elu1(v2); v3 = elu1(v3); }
            if (EPI == 2) { v0 = elu1(v0); v1 = elu1(v1); v2 = elu1(v2); v3 = elu1(v3); }
            size_t o0 = (size_t)row * ldC + col;
            size_t o1 = (size_t)(row + 8) * ldC + col;
            if (WF32) {
                *reinterpret_cast<float2*>(C + o0) = make_float2(v0, v1);
                *reinterpret_cast<float2*>(C + o1) = make_float2(v2, v3);
            }
            if (WSPLIT) {
                uint32_t hi, lo;
                cvt_split2(v0, v1, hi, lo);
                *reinterpret_cast<uint32_t*>(Ch + o0) = hi;
                *reinterpret_cast<uint32_t*>(Cl + o0) = lo;
                cvt_split2(v2, v3, hi, lo);
                *reinterpret_cast<uint32_t*>(Ch + o1) = hi;
                *reinterpret_cast<uint32_t*>(Cl + o1) = lo;
            }
        }
    }
}

// ---------------- split+pad prep: fp32 [R,C] -> bf16 hi/lo [R,Cp] ----------
__global__ __launch_bounds__(256) void split_pad(
    const float* __restrict__ src, __nv_bfloat16* __restrict__ dh,
    __nv_bfloat16* __restrict__ dl, int C, int Cp, size_t total)
{
    size_t i = (size_t)blockIdx.x * blockDim.x + threadIdx.x;
    if (i >= total) return;
    int c = (int)(i % Cp);
    size_t r = i / Cp;
    float v = (c < C) ? src[r * C + c] : 0.f;
    __nv_bfloat16 h = __float2bfloat16(v);
    dh[i] = h;
    dl[i] = __float2bfloat16(v - __bfloat162float(h));
}

// ---------------- attention: column-mean weights; weighted x -> xw split ----
__global__ __launch_bounds__(256) void attn2_kernel(
    const float* __restrict__ qk, const float* __restrict__ x,
    __nv_bfloat16* __restrict__ xwh, __nv_bfloat16* __restrict__ xwl)
{
    const int g = blockIdx.x;
    const int tid = threadIdx.x;
    __shared__ float qs[16][257];
    __shared__ float ks[16][257];
    __shared__ float sc[16][17];
    __shared__ float cw[16];
    const float* base = qk + (size_t)g * GSZ * 1024;
    const float* xbase = x + (size_t)g * GSZ * 512;

    for (int h = 0; h < 2; h++) {
        for (int i = tid; i < 16 * 256; i += 256) {
            int t = i >> 8, d = i & 255;
            qs[t][d] = base[t * 1024 + h * 256 + d];
            ks[t][d] = base[t * 1024 + 512 + h * 256 + d];
        }
        __syncthreads();
        {
            int tq = tid >> 4, tk = tid & 15;
            float a = 0.f;
#pragma unroll 8
            for (int d = 0; d < 256; d++) a += qs[tq][d] * ks[tk][d];
            sc[tq][tk] = a * 0.0625f;
        }
        __syncthreads();
        if (tid < 16) {
            int tq = tid;
            float mx = -1e30f;
            for (int tk = 0; tk < 16; tk++) mx = fmaxf(mx, sc[tq][tk]);
            float s = 0.f;
            for (int tk = 0; tk < 16; tk++) {
                float e = expf(sc[tq][tk] - mx);
                sc[tq][tk] = e;
                s += e;
            }
            float inv = 1.f / s;
            for (int tk = 0; tk < 16; tk++) sc[tq][tk] *= inv;
        }
        __syncthreads();
        if (tid < 16) {
            int tk = tid;
            float s = 0.f;
            for (int tq = 0; tq < 16; tq++) s += sc[tq][tk];
            cw[tk] = s * 0.0625f;
        }
        __syncthreads();
        for (int it = 0; it < 2; it++) {
            int d = tid + it * 256;
            float a = 0.f;
#pragma unroll
            for (int tk = 0; tk < 16; tk++)
                a += cw[tk] * xbase[tk * 512 + d];
            size_t o = (size_t)h * NGR * EFULL + (size_t)g * EFULL + d;
            __nv_bfloat16 hb = __float2bfloat16(a);
            xwh[o] = hb;
            xwl[o] = __float2bfloat16(a - __bfloat162float(hb));
        }
        __syncthreads();
    }
}

// ---------------- g head final: q_jt[g] = dot(hg[g], w4) + b4
__global__ __launch_bounds__(256) void ghead4_kernel(
    const float* __restrict__ hg, const float* __restrict__ w,
    const float* __restrict__ b, float* __restrict__ out)
{
    int row = blockIdx.x * 8 + (threadIdx.x >> 5);
    int lane = threadIdx.x & 31;
    float acc = 0.f;
    for (int k = lane; k < 256; k += 32)
        acc += hg[(size_t)row * 256 + k] * w[k];
#pragma unroll
    for (int o = 16; o > 0; o >>= 1)
        acc += __shfl_xor_sync(0xffffffffu, acc, o);
    if (lane == 0) out[row] = acc + b[0];
}

// ---------------- alt_val = pe + km[group] - key1/16 -> split bf16 ----------
__global__ __launch_bounds__(256) void altval_kernel(
    const float* __restrict__ pe, const float* __restrict__ key1,
    const float* __restrict__ km, __nv_bfloat16* __restrict__ ah,
    __nv_bfloat16* __restrict__ al)
{
    size_t i = (size_t)blockIdx.x * blockDim.x + threadIdx.x;
    int d = (int)(i & 511);
    size_t g = i >> 13;   // (i / 512) / 16
    float v = pe[i] + km[g * EFULL + d] - key1[i] * 0.0625f;
    __nv_bfloat16 h = __float2bfloat16(v);
    ah[i] = h;
    al[i] = __float2bfloat16(v - __bfloat162float(h));
}

// ---------------- alt_q = hp @ w3^T + b3 (256 -> 2)
__global__ __launch_bounds__(256) void altq_kernel(
    const float* __restrict__ hp, const float* __restrict__ w,
    const float* __restrict__ b, float* __restrict__ out)
{
    int row = blockIdx.x * 8 + (threadIdx.x >> 5);
    int lane = threadIdx.x & 31;
    float a0 = 0.f, a1 = 0.f;
    for (int k = lane; k < 256; k += 32) {
        float h = hp[(size_t)row * 256 + k];
        a0 += h * w[k];
        a1 += h * w[256 + k];
    }
#pragma unroll
    for (int o = 16; o > 0; o >>= 1) {
        a0 += __shfl_xor_sync(0xffffffffu, a0, o);
        a1 += __shfl_xor_sync(0xffffffffu, a1, o);
    }
    if (lane == 0) {
        out[(size_t)row * 2 + 0] = a0 + b[0];
        out[(size_t)row * 2 + 1] = a1 + b[1];
    }
}

// ================================================================ host launch
extern "C" void kernel_launch(void* const* d_in, const int* in_sizes, int n_in,
                              void* d_out, int out_size)
{
    const float* pe       = (const float*)d_in[0];
    const float* peA      = (const float*)d_in[1];
    const float* attn_in_w  = (const float*)d_in[2];
    const float* attn_in_b  = (const float*)d_in[3];
    const float* attn_out_w = (const float*)d_in[4];
    const float* attn_out_b = (const float*)d_in[5];
    const float* p1w1 = (const float*)d_in[6];  const float* p1b1 = (const float*)d_in[7];
    const float* p1w2 = (const float*)d_in[8];  const float* p1b2 = (const float*)d_in[9];
    const float* p1w3 = (const float*)d_in[10]; const float* p1b3 = (const float*)d_in[11];
    const float* p1w4 = (const float*)d_in[12]; const float* p1b4 = (const float*)d_in[13];
    const float* gw1 = (const float*)d_in[14];  const float* gb1 = (const float*)d_in[15];
    const float* gw2 = (const float*)d_in[16];  const float* gb2 = (const float*)d_in[17];
    const float* gw3 = (const float*)d_in[18];  const float* gb3 = (const float*)d_in[19];
    const float* gw4 = (const float*)d_in[20];  const float* gb4 = (const float*)d_in[21];
    const float* p2w1 = (const float*)d_in[22]; const float* p2b1 = (const float*)d_in[23];
    const float* p2w2 = (const float*)d_in[24]; const float* p2b2 = (const float*)d_in[25];
    const float* p2w3 = (const float*)d_in[26]; const float* p2b3 = (const float*)d_in[27];
    float* out = (float*)d_out;

    #define SYM(T, v, s) T* v; cudaGetSymbolAddress((void**)&v, s)
    SYM(__nv_bfloat16, peAh, g_peAh); SYM(__nv_bfloat16, peAl, g_peAl);
    SYM(__nv_bfloat16, h1h, g_h1h);   SYM(__nv_bfloat16, h1l, g_h1l);
    SYM(__nv_bfloat16, h2h, g_h2h);   SYM(__nv_bfloat16, h2l, g_h2l);
    SYM(float, key1, g_key1);
    SYM(__nv_bfloat16, key1h, g_key1h); SYM(__nv_bfloat16, key1l, g_key1l);
    SYM(float, qk, g_qk);
    SYM(__nv_bfloat16, xwh, g_xwh);   SYM(__nv_bfloat16, xwl, g_xwl);
    SYM(__nv_bfloat16, omh, g_omh);   SYM(__nv_bfloat16, oml, g_oml);
    SYM(float, km, g_km);
    SYM(__nv_bfloat16, kmh, g_kmh);   SYM(__nv_bfloat16, kml, g_kml);
    SYM(__nv_bfloat16, hgah, g_hgah); SYM(__nv_bfloat16, hgal, g_hgal);
    SYM(__nv_bfloat16, hgbh, g_hgbh); SYM(__nv_bfloat16, hgbl, g_hgbl);
    SYM(float, hgaf, g_hgaf);
    SYM(__nv_bfloat16, alth, g_alth); SYM(__nv_bfloat16, altl, g_altl);
    SYM(float, h2f, g_h2f);
    SYM(__nv_bfloat16, wph, g_wph);   SYM(__nv_bfloat16, wpl, g_wpl);

    cudaFuncSetAttribute(gemm_bf16<1,false,true>,  cudaFuncAttributeMaxDynamicSharedMemorySize, SMEM_TOT);
    cudaFuncSetAttribute(gemm_bf16<2,false,true>,  cudaFuncAttributeMaxDynamicSharedMemorySize, SMEM_TOT);
    cudaFuncSetAttribute(gemm_bf16<0,true,true>,   cudaFuncAttributeMaxDynamicSharedMemorySize, SMEM_TOT);
    cudaFuncSetAttribute(gemm_bf16<0,true,false>,  cudaFuncAttributeMaxDynamicSharedMemorySize, SMEM_TOT);
    cudaFuncSetAttribute(gemm_bf16<0,false,true>,  cudaFuncAttributeMaxDynamicSharedMemorySize, SMEM_TOT);
    cudaFuncSetAttribute(gemm_bf16<1,true,false>,  cudaFuncAttributeMaxDynamicSharedMemorySize, SMEM_TOT);

    const int TB = 256;
    #define SPLIT(src, dsth, dstl, R, C, Cp) do {                              \
        size_t tot = (size_t)(R) * (Cp);                                       \
        split_pad<<<(unsigned)((tot + 255) / 256), TB>>>(src, dsth, dstl, C, Cp, tot); \
    } while (0)

    // ---- prep: split weights + padded peA ----
    SPLIT(peA, peAh, peAl, NTOK, 514, KPAD1);
    SPLIT(p1w1, wph + OW_P1W1, wpl + OW_P1W1, 256, 514, KPAD1);
    SPLIT(p1w2, wph + OW_P1W2, wpl + OW_P1W2, 256, 256, 256);
    SPLIT(p1w3, wph + OW_P1W3, wpl + OW_P1W3, 256, 256, 256);
    SPLIT(p1w4, wph + OW_P1W4, wpl + OW_P1W4, 512, 256, 256);
    SPLIT(attn_in_w, wph + OW_WQK, wpl + OW_WQK, 1024, 512, 512);
    SPLIT(attn_in_w + (size_t)1024 * 512, wph + OW_WV0, wpl + OW_WV0, 256, 512, 512);
    SPLIT(attn_in_w + (size_t)1280 * 512, wph + OW_WV1, wpl + OW_WV1, 256, 512, 512);
    SPLIT(attn_out_w, wph + OW_WOUT, wpl + OW_WOUT, 512, 512, 512);
    SPLIT(gw1, wph + OW_GW1, wpl + OW_GW1, 256, 512, 512);
    SPLIT(gw2, wph + OW_GW2, wpl + OW_GW2, 256, 256, 256);
    SPLIT(gw3, wph + OW_GW3, wpl + OW_GW3, 256, 256, 256);
    SPLIT(p2w1, wph + OW_P2W1, wpl + OW_P2W1, 256, 512, 512);
    SPLIT(p2w2, wph + OW_P2W2, wpl + OW_P2W2, 256, 256, 256);

    #define GRID(Mv, Nv) dim3((Nv) / 128, (Mv) / 128)

    // phi1 chain
    gemm_bf16<1,false,true><<<GRID(NTOK, HIDC), TB, SMEM_TOT>>>(
        peAh, peAl, wph + OW_P1W1, wpl + OW_P1W1, p1b1, nullptr, h1h, h1l, KPAD1, HIDC);
    gemm_bf16<2,false,true><<<GRID(NTOK, HIDC), TB, SMEM_TOT>>>(
        h1h, h1l, wph + OW_P1W2, wpl + OW_P1W2, p1b2, nullptr, h2h, h2l, HIDC, HIDC);
    gemm_bf16<1,false,true><<<GRID(NTOK, HIDC), TB, SMEM_TOT>>>(
        h2h, h2l, wph + OW_P1W3, wpl + OW_P1W3, p1b3, nullptr, h1h, h1l, HIDC, HIDC);
    gemm_bf16<0,true,true><<<GRID(NTOK, EFULL), TB, SMEM_TOT>>>(
        h1h, h1l, wph + OW_P1W4, wpl + OW_P1W4, p1b4, key1, key1h, key1l, HIDC, EFULL);

    // q,k projection + attention (v eliminated algebraically)
    gemm_bf16<0,true,false><<<GRID(NTOK, 1024), TB, SMEM_TOT>>>(
        key1h, key1l, wph + OW_WQK, wpl + OW_WQK, attn_in_b, qk, nullptr, nullptr, EFULL, 1024);
    attn2_kernel<<<NGR, TB>>>(qk, key1, xwh, xwl);
    // per-head v projection: o_mean = xw_h @ Wv_h^T + bv_h
    gemm_bf16<0,false,true><<<GRID(NGR, 256), TB, SMEM_TOT>>>(
        xwh, xwl, wph + OW_WV0, wpl + OW_WV0, attn_in_b + 1024,
        nullptr, omh, oml, EFULL, EFULL);
    gemm_bf16<0,false,true><<<GRID(NGR, 256), TB, SMEM_TOT>>>(
        xwh + (size_t)NGR * EFULL, xwl + (size_t)NGR * EFULL,
        wph + OW_WV1, wpl + OW_WV1, attn_in_b + 1280,
        nullptr, omh + 256, oml + 256, EFULL, EFULL);
    // km = omean @ Wo^T + bo
    gemm_bf16<0,true,true><<<GRID(NGR, EFULL), TB, SMEM_TOT>>>(
        omh, oml, wph + OW_WOUT, wpl + OW_WOUT, attn_out_b, km, kmh, kml, EFULL, EFULL);

    // g head -> q_jt at out[0 .. 4096)
    gemm_bf16<1,false,true><<<GRID(NGR, HIDC), TB, SMEM_TOT>>>(
        kmh, kml, wph + OW_GW1, wpl + OW_GW1, gb1, nullptr, hgah, hgal, EFULL, HIDC);
    gemm_bf16<1,false,true><<<GRID(NGR, HIDC), TB, SMEM_TOT>>>(
        hgah, hgal, wph + OW_GW2, wpl + OW_GW2, gb2, nullptr, hgbh, hgbl, HIDC, HIDC);
    gemm_bf16<1,true,false><<<GRID(NGR, HIDC), TB, SMEM_TOT>>>(
        hgbh, hgbl, wph + OW_GW3, wpl + OW_GW3, gb3, hgaf, nullptr, nullptr, HIDC, HIDC);
    ghead4_kernel<<<NGR / 8, TB>>>(hgaf, gw4, gb4, out);

    // alt path -> alt_q at out[4096 ..)
    altval_kernel<<<(unsigned)(((size_t)NTOK * EFULL) / TB), TB>>>(pe, key1, km, alth, altl);
    gemm_bf16<1,false,true><<<GRID(NTOK, HIDC), TB, SMEM_TOT>>>(
        alth, altl, wph + OW_P2W1, wpl + OW_P2W1, p2b1, nullptr, h1h, h1l, EFULL, HIDC);
    gemm_bf16<1,true,false><<<GRID(NTOK, HIDC), TB, SMEM_TOT>>>(
        h1h, h1l, wph + OW_P2W2, wpl + OW_P2W2, p2b2, h2f, nullptr, nullptr, HIDC, HIDC);
    altq_kernel<<<NTOK / 8, TB>>>(h2f, p2w3, p2b3, out + NGR);
}